// round 2
// baseline (speedup 1.0000x reference)
#include <cuda_runtime.h>
#include <math.h>

#define FEAT 512
#define MAX_NSEG 65536
#define MAX_ROWS 2048   // max atoms per segment supported (actual max ~30 for Poisson(8))

__device__ float g_v[FEAT];
__device__ float g_c;
__device__ int   g_seg_start[MAX_NSEG + 1];

// ---------------------------------------------------------------------------
// Kernel 1: v[d] = sum_e W[e,d] * q[e]   (torch Linear: y = x @ W^T + b)
//           c    = sum_e b[e] * q[e]
// ---------------------------------------------------------------------------
__global__ __launch_bounds__(FEAT)
void compute_v_kernel(const float* __restrict__ W,
                      const float* __restrict__ b,
                      const float* __restrict__ q) {
    int d = threadIdx.x;               // 512 threads
    __shared__ float sq[FEAT];
    __shared__ float red[FEAT];
    sq[d] = q[d];
    __syncthreads();

    float acc = 0.0f;
    #pragma unroll 8
    for (int e = 0; e < FEAT; e++) {
        acc = fmaf(W[(size_t)e * FEAT + d], sq[e], acc);  // coalesced across d
    }
    g_v[d] = acc;

    red[d] = b[d] * sq[d];
    __syncthreads();
    for (int s = FEAT / 2; s > 0; s >>= 1) {
        if (d < s) red[d] += red[d + s];
        __syncthreads();
    }
    if (d == 0) g_c = red[0];
}

// ---------------------------------------------------------------------------
// Kernel 2: segment start offsets from the (sorted, int32) residue_index.
// g_seg_start[s] = first n with idx[n] >= s;  g_seg_start[nseg] = n_atoms.
// ---------------------------------------------------------------------------
__global__ void seg_offsets_kernel(const int* __restrict__ idx,
                                   int n, int nseg) {
    int i = blockIdx.x * blockDim.x + threadIdx.x;
    if (i >= n) return;
    int cur  = idx[i];
    int prev = (i == 0) ? -1 : idx[i - 1];
    if (cur  > nseg) cur  = nseg;     // safety clamp
    if (prev > nseg) prev = nseg;
    for (int s = prev + 1; s <= cur; s++) {
        g_seg_start[s] = i;
    }
    if (i == n - 1) {
        for (int s = cur + 1; s <= nseg; s++) {
            g_seg_start[s] = n;
        }
    }
}

// ---------------------------------------------------------------------------
// Kernel 3 (fused): one block per segment, 512 threads = 16 warps.
// Phase 1: warp w computes score of rows start+w, start+w+16, ... (row cached
//          in registers for the first iteration — covers >99.6% of rows).
// Phase 2: block softmax (max, exp, sum) over the segment's scores in smem.
// Phase 3: each warp accumulates attn * row into a 512-float smem tile
//          (shared atomics), then one coalesced global write.
// ---------------------------------------------------------------------------
__global__ __launch_bounds__(512)
void fused_attention_pool_kernel(const float* __restrict__ feat,
                                 float* __restrict__ out) {
    const int s    = blockIdx.x;
    const int tid  = threadIdx.x;
    const int wid  = tid >> 5;
    const int lane = tid & 31;

    __shared__ float sv[FEAT];
    __shared__ float sout[FEAT];
    __shared__ float sscores[MAX_ROWS];
    __shared__ float sred[32];

    sv[tid]   = g_v[tid];
    sout[tid] = 0.0f;
    __syncthreads();

    const int start = g_seg_start[s];
    const int end   = g_seg_start[s + 1];
    int cnt = end - start;
    if (cnt > MAX_ROWS) cnt = MAX_ROWS;   // safety clamp (never hit for this data)

    float* orow = out + (size_t)s * FEAT;

    if (cnt <= 0) {
        // empty segment: segment_sum == 0
        orow[tid] = 0.0f;
        return;
    }

    const float c = g_c;

    // ---- Phase 1: scores (warp-per-row, register-cache first row) ----
    float4 cache[4];
    #pragma unroll
    for (int j = 0; j < 4; j++) cache[j] = make_float4(0.f, 0.f, 0.f, 0.f);

    for (int r = wid; r < cnt; r += 16) {
        const float4* row = (const float4*)(feat + (size_t)(start + r) * FEAT);
        float acc = 0.0f;
        #pragma unroll
        for (int j = 0; j < 4; j++) {
            float4 f = row[j * 32 + lane];
            int base = (j * 32 + lane) * 4;
            acc = fmaf(f.x, sv[base + 0], acc);
            acc = fmaf(f.y, sv[base + 1], acc);
            acc = fmaf(f.z, sv[base + 2], acc);
            acc = fmaf(f.w, sv[base + 3], acc);
            if (r == wid) cache[j] = f;    // keep first row in registers
        }
        #pragma unroll
        for (int o = 16; o > 0; o >>= 1)
            acc += __shfl_xor_sync(0xffffffffu, acc, o);
        if (lane == 0) sscores[r] = acc + c;
    }
    __syncthreads();

    // ---- Phase 2a: block max ----
    float mx = -INFINITY;
    for (int r = tid; r < cnt; r += 512) mx = fmaxf(mx, sscores[r]);
    #pragma unroll
    for (int o = 16; o > 0; o >>= 1)
        mx = fmaxf(mx, __shfl_xor_sync(0xffffffffu, mx, o));
    if (lane == 0) sred[wid] = mx;
    __syncthreads();
    if (wid == 0) {
        float m = (lane < 16) ? sred[lane] : -INFINITY;
        #pragma unroll
        for (int o = 16; o > 0; o >>= 1)
            m = fmaxf(m, __shfl_xor_sync(0xffffffffu, m, o));
        if (lane == 0) sred[0] = m;
    }
    __syncthreads();
    mx = sred[0];

    // ---- Phase 2b: exp + block sum ----
    float sum = 0.0f;
    for (int r = tid; r < cnt; r += 512) {
        float e = expf(sscores[r] - mx);
        sscores[r] = e;
        sum += e;
    }
    #pragma unroll
    for (int o = 16; o > 0; o >>= 1)
        sum += __shfl_xor_sync(0xffffffffu, sum, o);
    __syncthreads();                      // all reads of sred[0] (mx) done
    if (lane == 0) sred[wid] = sum;
    __syncthreads();
    if (wid == 0) {
        float t = (lane < 16) ? sred[lane] : 0.0f;
        #pragma unroll
        for (int o = 16; o > 0; o >>= 1)
            t += __shfl_xor_sync(0xffffffffu, t, o);
        if (lane == 0) sred[0] = t;
    }
    __syncthreads();
    const float inv_denom = 1.0f / sred[0];

    // ---- Phase 3: weighted accumulation into smem tile ----
    for (int r = wid; r < cnt; r += 16) {
        float w = sscores[r] * inv_denom;
        const float4* row = (const float4*)(feat + (size_t)(start + r) * FEAT);
        #pragma unroll
        for (int j = 0; j < 4; j++) {
            float4 f = (r == wid) ? cache[j] : row[j * 32 + lane];  // reg hit / L2 hit
            int base = (j * 32 + lane) * 4;
            atomicAdd(&sout[base + 0], w * f.x);
            atomicAdd(&sout[base + 1], w * f.y);
            atomicAdd(&sout[base + 2], w * f.z);
            atomicAdd(&sout[base + 3], w * f.w);
        }
    }
    __syncthreads();

    orow[tid] = sout[tid];
}

// ---------------------------------------------------------------------------
// Launch
// Inputs (metadata order): features [N,512] f32, residue_index [N] int32
//   (JAX default x64-disabled canonicalizes int64 -> int32),
//   proj_w [512,512] f32, proj_b [512] f32, query [512] f32
// Output: [NSEG, 512] f32
// ---------------------------------------------------------------------------
extern "C" void kernel_launch(void* const* d_in, const int* in_sizes, int n_in,
                              void* d_out, int out_size) {
    const float* features = (const float*)d_in[0];
    const int*   ridx     = (const int*)d_in[1];
    const float* proj_w   = (const float*)d_in[2];
    const float* proj_b   = (const float*)d_in[3];
    const float* query    = (const float*)d_in[4];
    float*       out      = (float*)d_out;

    const int n_atoms = in_sizes[1];           // residue_index element count
    const int nseg    = out_size / FEAT;

    compute_v_kernel<<<1, FEAT>>>(proj_w, proj_b, query);
    seg_offsets_kernel<<<(n_atoms + 255) / 256, 256>>>(ridx, n_atoms, nseg);
    fused_attention_pool_kernel<<<nseg, 512>>>(features, out);
}

// round 3
// speedup vs baseline: 5.2859x; 5.2859x over previous
#include <cuda_runtime.h>
#include <math.h>

#define FEAT       512
#define FEAT4      128            // FEAT / 4
#define MAX_NSEG   65536
#define VPART_BLKS 32
#define E_PER_BLK  16             // FEAT / VPART_BLKS

__device__ float g_v[FEAT];
__device__ float g_vpart[VPART_BLKS * FEAT];
__device__ float g_c;
__device__ int   g_seg_start[MAX_NSEG + 1];

// ---------------------------------------------------------------------------
// Kernel 1a: partial v = W^T q over a 16-row slice of W per block.
// ---------------------------------------------------------------------------
__global__ __launch_bounds__(FEAT)
void compute_v_part_kernel(const float* __restrict__ W,
                           const float* __restrict__ q) {
    const int d = threadIdx.x;
    const int b = blockIdx.x;
    float acc = 0.0f;
    #pragma unroll
    for (int i = 0; i < E_PER_BLK; i++) {
        int e = b * E_PER_BLK + i;
        acc = fmaf(W[(size_t)e * FEAT + d], __ldg(&q[e]), acc);  // coalesced across d
    }
    g_vpart[b * FEAT + d] = acc;
}

// ---------------------------------------------------------------------------
// Kernel 1b: reduce partials -> g_v;  c = b . q
// ---------------------------------------------------------------------------
__global__ __launch_bounds__(FEAT)
void compute_v_final_kernel(const float* __restrict__ b,
                            const float* __restrict__ q) {
    const int d = threadIdx.x;
    float acc = 0.0f;
    #pragma unroll
    for (int p = 0; p < VPART_BLKS; p++) acc += g_vpart[p * FEAT + d];
    g_v[d] = acc;

    __shared__ float red[FEAT];
    red[d] = b[d] * q[d];
    __syncthreads();
    for (int s = FEAT / 2; s > 0; s >>= 1) {
        if (d < s) red[d] += red[d + s];
        __syncthreads();
    }
    if (d == 0) g_c = red[0];
}

// ---------------------------------------------------------------------------
// Kernel 2: segment start offsets from the (sorted, int32) residue_index.
// ---------------------------------------------------------------------------
__global__ void seg_offsets_kernel(const int* __restrict__ idx,
                                   int n, int nseg) {
    int i = blockIdx.x * blockDim.x + threadIdx.x;
    if (i >= n) return;
    int cur  = idx[i];
    int prev = (i == 0) ? -1 : idx[i - 1];
    if (cur  > nseg) cur  = nseg;
    if (prev > nseg) prev = nseg;
    for (int s = prev + 1; s <= cur; s++) g_seg_start[s] = i;
    if (i == n - 1) {
        for (int s = cur + 1; s <= nseg; s++) g_seg_start[s] = n;
    }
}

// ---------------------------------------------------------------------------
// Kernel 3: warp-per-segment online-softmax attention pooling.
// Each warp streams its segment's rows once:
//   score = row.v + c (warp allreduce), online max/denom/weighted-sum update.
// Lane L owns feature float4s {L, 32+L, 64+L, 96+L} (coalesced 512B per LDG).
// No __syncthreads, no atomics, features read exactly once.
// ---------------------------------------------------------------------------
#define WARPS_PER_BLK 8

__global__ __launch_bounds__(WARPS_PER_BLK * 32)
void warp_pool_kernel(const float* __restrict__ feat,
                      float* __restrict__ out,
                      int nseg) {
    const int wid  = threadIdx.x >> 5;
    const int lane = threadIdx.x & 31;
    const int s    = blockIdx.x * WARPS_PER_BLK + wid;
    if (s >= nseg) return;

    const int start = g_seg_start[s];
    const int end   = g_seg_start[s + 1];

    // register-resident v slice
    const float4* v4 = (const float4*)g_v;
    const float4 v0 = v4[lane];
    const float4 v1 = v4[32 + lane];
    const float4 v2 = v4[64 + lane];
    const float4 v3 = v4[96 + lane];
    const float  c  = g_c;

    float m   = -INFINITY;
    float den = 0.0f;
    float4 a0 = make_float4(0.f, 0.f, 0.f, 0.f);
    float4 a1 = a0, a2 = a0, a3 = a0;

    const float4* feat4 = (const float4*)feat;

    for (int r = start; r < end; r++) {
        const float4* row = feat4 + (size_t)r * FEAT4;
        float4 f0 = row[lane];
        float4 f1 = row[32 + lane];
        float4 f2 = row[64 + lane];
        float4 f3 = row[96 + lane];

        float p = f0.x * v0.x;
        p = fmaf(f0.y, v0.y, p); p = fmaf(f0.z, v0.z, p); p = fmaf(f0.w, v0.w, p);
        p = fmaf(f1.x, v1.x, p); p = fmaf(f1.y, v1.y, p); p = fmaf(f1.z, v1.z, p); p = fmaf(f1.w, v1.w, p);
        p = fmaf(f2.x, v2.x, p); p = fmaf(f2.y, v2.y, p); p = fmaf(f2.z, v2.z, p); p = fmaf(f2.w, v2.w, p);
        p = fmaf(f3.x, v3.x, p); p = fmaf(f3.y, v3.y, p); p = fmaf(f3.z, v3.z, p); p = fmaf(f3.w, v3.w, p);

        #pragma unroll
        for (int o = 16; o > 0; o >>= 1)
            p += __shfl_xor_sync(0xffffffffu, p, o);

        const float sc    = p + c;
        const float mn    = fmaxf(m, sc);
        const float scale = __expf(m - mn);   // m=-inf on first row -> 0
        const float wr    = __expf(sc - mn);
        den = den * scale + wr;

        a0.x = fmaf(wr, f0.x, a0.x * scale); a0.y = fmaf(wr, f0.y, a0.y * scale);
        a0.z = fmaf(wr, f0.z, a0.z * scale); a0.w = fmaf(wr, f0.w, a0.w * scale);
        a1.x = fmaf(wr, f1.x, a1.x * scale); a1.y = fmaf(wr, f1.y, a1.y * scale);
        a1.z = fmaf(wr, f1.z, a1.z * scale); a1.w = fmaf(wr, f1.w, a1.w * scale);
        a2.x = fmaf(wr, f2.x, a2.x * scale); a2.y = fmaf(wr, f2.y, a2.y * scale);
        a2.z = fmaf(wr, f2.z, a2.z * scale); a2.w = fmaf(wr, f2.w, a2.w * scale);
        a3.x = fmaf(wr, f3.x, a3.x * scale); a3.y = fmaf(wr, f3.y, a3.y * scale);
        a3.z = fmaf(wr, f3.z, a3.z * scale); a3.w = fmaf(wr, f3.w, a3.w * scale);

        m = mn;
    }

    const float inv = (end > start) ? (1.0f / den) : 0.0f;  // empty -> zeros
    float4* orow = (float4*)(out + (size_t)s * FEAT);
    a0.x *= inv; a0.y *= inv; a0.z *= inv; a0.w *= inv;
    a1.x *= inv; a1.y *= inv; a1.z *= inv; a1.w *= inv;
    a2.x *= inv; a2.y *= inv; a2.z *= inv; a2.w *= inv;
    a3.x *= inv; a3.y *= inv; a3.z *= inv; a3.w *= inv;
    orow[lane]      = a0;
    orow[32 + lane] = a1;
    orow[64 + lane] = a2;
    orow[96 + lane] = a3;
}

// ---------------------------------------------------------------------------
// Launch
// Inputs: features [N,512] f32, residue_index [N] int32,
//         proj_w [512,512] f32, proj_b [512] f32, query [512] f32
// Output: [NSEG, 512] f32
// ---------------------------------------------------------------------------
extern "C" void kernel_launch(void* const* d_in, const int* in_sizes, int n_in,
                              void* d_out, int out_size) {
    const float* features = (const float*)d_in[0];
    const int*   ridx     = (const int*)d_in[1];
    const float* proj_w   = (const float*)d_in[2];
    const float* proj_b   = (const float*)d_in[3];
    const float* query    = (const float*)d_in[4];
    float*       out      = (float*)d_out;

    const int n_atoms = in_sizes[1];
    const int nseg    = out_size / FEAT;

    compute_v_part_kernel<<<VPART_BLKS, FEAT>>>(proj_w, query);
    compute_v_final_kernel<<<1, FEAT>>>(proj_b, query);
    seg_offsets_kernel<<<(n_atoms + 255) / 256, 256>>>(ridx, n_atoms, nseg);

    const int nblk = (nseg + WARPS_PER_BLK - 1) / WARPS_PER_BLK;
    warp_pool_kernel<<<nblk, WARPS_PER_BLK * 32>>>(features, out, nseg);
}